// round 6
// baseline (speedup 1.0000x reference)
#include <cuda_runtime.h>
#include <cuda_bf16.h>
#include <cstdint>

// Problem constants
#define BB 64
#define KK 64
#define DD 128
#define HH 128
#define TT 4
#define ROWS (BB*KK)        // 4096
#define EPSLN 1e-5f

// ---------------- scratch (no allocations allowed) ----------------
__device__ float g_HDS[ROWS*DD];
__device__ float g_H  [ROWS*DD];
__device__ float g_W  [ROWS*TT];                 // [row][tau]
__device__ __nv_bfloat16 g_Ab [TT*ROWS*HH];
__device__ __nv_bfloat16 g_Bb [TT*ROWS*HH];
__device__ __nv_bfloat16 g_Sb [ROWS*TT*HH];      // [row][tau*128+n]

// prepped weights: bf16, [n][k-pair] chunked (4096 words per 64-k chunk)
#define W_WS1   0
#define W_WS2   8192
#define W_WU2   16384
#define W_WI3   24576
#define W_WU1   57344
#define W_WI1   73728
#define W_WI2F  139264
#define W_TOTAL 172032
__device__ __align__(16) uint32_t g_Wp[W_TOTAL];

// ---------------- helpers ----------------
__device__ __forceinline__ uint32_t pk2(float lo, float hi){
    __nv_bfloat162 v = __floats2bfloat162_rn(lo, hi);
    return *(uint32_t*)&v;
}
__device__ __forceinline__ uint32_t addrelu2(uint32_t a, uint32_t b){
    __nv_bfloat162 av = *(__nv_bfloat162*)&a;
    __nv_bfloat162 bv = *(__nv_bfloat162*)&b;
    __nv_bfloat162 z  = __float2bfloat162_rn(0.f);
    __nv_bfloat162 r  = __hmax2(__hadd2(av, bv), z);
    return *(uint32_t*)&r;
}
__device__ __forceinline__ void mma16816(float c[4], const uint32_t a[4],
                                         uint32_t b0, uint32_t b1){
    asm volatile(
        "mma.sync.aligned.m16n8k16.row.col.f32.bf16.bf16.f32 "
        "{%0,%1,%2,%3}, {%4,%5,%6,%7}, {%8,%9}, {%0,%1,%2,%3};\n"
        : "+f"(c[0]), "+f"(c[1]), "+f"(c[2]), "+f"(c[3])
        : "r"(a[0]), "r"(a[1]), "r"(a[2]), "r"(a[3]), "r"(b0), "r"(b1));
}
__device__ __forceinline__ void ldmx4(uint32_t r[4], uint32_t a){
    asm volatile("ldmatrix.sync.aligned.m8n8.x4.shared.b16 {%0,%1,%2,%3}, [%4];"
        : "=r"(r[0]), "=r"(r[1]), "=r"(r[2]), "=r"(r[3]) : "r"(a));
}
__device__ __forceinline__ uint32_t s2u(const void* p){
    return (uint32_t)__cvta_generic_to_shared((void*)p);
}

// ---------------- weight prep: fp32 [K][128] -> bf16 [chunk][n][kw] ---------
__global__ void __launch_bounds__(256) prep_weights(
    const float* __restrict__ ws1, const float* __restrict__ ws2,
    const float* __restrict__ wu2, const float* __restrict__ wi3,
    const float* __restrict__ wu1, const float* __restrict__ wi1,
    const float* __restrict__ wi2)
{
    int idx = blockIdx.x*256 + threadIdx.x;
    if (idx >= W_TOTAL) return;
    const float* src;
    int local;
    if (idx < W_WS2)       { src = ws1; local = idx - W_WS1; }
    else if (idx < W_WU2)  { src = ws2; local = idx - W_WS2; }
    else if (idx < W_WI3)  { src = wu2; local = idx - W_WU2; }
    else if (idx < W_WU1)  { src = wi3; local = idx - W_WI3; }
    else if (idx < W_WI1)  { src = wu1; local = idx - W_WU1; }
    else if (idx < W_WI2F) {
        int l = idx - W_WI1;
        int tau = l >> 14;               // 16384 words per tau
        src = wi1 + (size_t)tau*256*128;
        local = l & 16383;
    } else {
        // wi2 flat: [tau][n:128][w:64]
        int l = idx - W_WI2F;
        int tau = l >> 13;               // 8192 per tau
        int r = l & 8191;
        int n = r >> 6, w = r & 63;
        const float* s = wi2 + (size_t)tau*16384;
        g_Wp[idx] = pk2(s[(size_t)(2*w)*128 + n], s[(size_t)(2*w+1)*128 + n]);
        return;
    }
    int c = local >> 12;                 // 4096 words per chunk
    int r = local & 4095;
    int n = r >> 5, w = r & 31;
    int k = c*64 + 2*w;
    g_Wp[idx] = pk2(src[(size_t)k*128 + n], src[(size_t)(k+1)*128 + n]);
}

// ---------------- unit GEMM chunk (16 rows x 128 n x 64 k) ------------------
// 8 warps: warp w covers n-tile w*16 (nt in {0,1} of 8 cols). Rows 0..15.
#define GSTR 36

__device__ __forceinline__ void ug16(
    float (&c)[2][4], char* sm, uint32_t smB, int wtOff,
    int aOff, int astr, int aChunkOff,
    const uint32_t* __restrict__ WgChunk, int tid)
{
    uint32_t* Wt = (uint32_t*)(sm + wtOff);
    #pragma unroll
    for (int l = 0; l < 4; l++) {
        int u = tid + l*256;             // uint4 index (1024)
        int n = u >> 3, w0 = (u & 7) * 4;
        *(uint4*)&Wt[n*GSTR + w0] = *(const uint4*)&WgChunk[u*4];
    }
    __syncthreads();
    int lane = tid & 31, wid = tid >> 5;
    int lA_row = lane & 15, lA_kw = (lane >> 4) << 2;
    int lB_row = (lane & 7) + ((lane >> 4) << 3);
    int lB_kw  = ((lane >> 3) & 1) << 2;
    uint32_t AsB = smB + aOff, WtB = smB + (uint32_t)wtOff;
    #pragma unroll
    for (int kk = 0; kk < 4; kk++) {
        uint32_t wf[4], a[4];
        ldmx4(wf, WtB + ((wid*16 + lB_row)*GSTR + kk*8 + lB_kw)*4);
        ldmx4(a, AsB + (lA_row*astr + aChunkOff + kk*8 + lA_kw)*4);
        mma16816(c[0], a, wf[0], wf[1]);
        mma16816(c[1], a, wf[2], wf[3]);
    }
    __syncthreads();
}

// ---------------- megaA: LN128 + self-MLP + wi1 (16-row tiles, grid 256) ----
#define MA_HS   0                       // 16*128*4 = 8192
#define MA_XN   8192                    // 16*68*4 = 4352
#define MA_HB   12544                   // 4352
#define MA_T1   16896                   // 4352
#define MA_WT   21248                   // 128*36*4 = 18432
#define MA_TOT  39680

__global__ void __launch_bounds__(256) megaA_kernel(
    const float* __restrict__ h,
    const float* __restrict__ ls_g, const float* __restrict__ ls_b,
    const float* __restrict__ bs1, const float* __restrict__ bs2,
    const float* __restrict__ bi1,
    float* __restrict__ HDS, __nv_bfloat16* __restrict__ Ab,
    __nv_bfloat16* __restrict__ Bb)
{
    extern __shared__ char sm[];
    float* Hs = (float*)(sm + MA_HS);
    uint32_t* XN = (uint32_t*)(sm + MA_XN);
    uint32_t* HB = (uint32_t*)(sm + MA_HB);
    uint32_t* T1 = (uint32_t*)(sm + MA_T1);
    uint32_t smB = s2u(sm);
    int tid = threadIdx.x, lane = tid & 31, wid = tid >> 5;
    int rowBase = blockIdx.x * 16;
    int g = lane >> 2, q4 = lane & 3;
    int row0 = g, row1 = g + 8;

    // load h rows (fp32): 16 rows x 32 float4
    #pragma unroll
    for (int l = 0; l < 2; l++) {
        int u = tid + l*256;
        int r = u >> 5, q = u & 31;
        *(float4*)&Hs[r*128 + q*4] =
            *(const float4*)&h[(size_t)(rowBase+r)*128 + q*4];
    }
    __syncthreads();

    // LN128: warp per row, 2 passes
    {
        float4 gg = ((const float4*)ls_g)[lane];
        float4 bb = ((const float4*)ls_b)[lane];
        #pragma unroll
        for (int p = 0; p < 2; p++) {
            int r = wid + p*8;
            float4 v = *(float4*)&Hs[r*128 + lane*4];
            float s = v.x + v.y + v.z + v.w;
            #pragma unroll
            for (int o = 16; o; o >>= 1) s += __shfl_xor_sync(0xffffffffu, s, o);
            float mu = s * (1.0f/128.0f);
            float dx = v.x-mu, dy = v.y-mu, dz = v.z-mu, dw = v.w-mu;
            float q = dx*dx + dy*dy + dz*dz + dw*dw;
            #pragma unroll
            for (int o = 16; o; o >>= 1) q += __shfl_xor_sync(0xffffffffu, q, o);
            float rs = rsqrtf(q * (1.0f/128.0f) + EPSLN);
            XN[r*68 + lane*2]   = pk2(dx*rs*gg.x + bb.x, dy*rs*gg.y + bb.y);
            XN[r*68 + lane*2+1] = pk2(dz*rs*gg.z + bb.z, dw*rs*gg.w + bb.w);
            HB[r*68 + lane*2]   = pk2(v.x, v.y);
            HB[r*68 + lane*2+1] = pk2(v.z, v.w);
        }
    }

    // unit 1: T1 = relu(XN @ ws1 + bs1) -> smem bf16
    {
        float c[2][4] = {};
        ug16(c, sm, smB, MA_WT, MA_XN, 68, 0,  g_Wp + W_WS1, tid);
        ug16(c, sm, smB, MA_WT, MA_XN, 68, 32, g_Wp + W_WS1 + 4096, tid);
        #pragma unroll
        for (int nt = 0; nt < 2; nt++) {
            int n0 = wid*16 + nt*8 + 2*q4;
            float2 bv = *(const float2*)&bs1[n0];
            T1[row0*68 + (n0>>1)] =
                pk2(fmaxf(c[nt][0]+bv.x,0.f), fmaxf(c[nt][1]+bv.y,0.f));
            T1[row1*68 + (n0>>1)] =
                pk2(fmaxf(c[nt][2]+bv.x,0.f), fmaxf(c[nt][3]+bv.y,0.f));
        }
    }

    // unit 2: HDS = h + T1 @ ws2 + bs2 -> gmem fp32
    {
        float c[2][4] = {};
        ug16(c, sm, smB, MA_WT, MA_T1, 68, 0,  g_Wp + W_WS2, tid);
        ug16(c, sm, smB, MA_WT, MA_T1, 68, 32, g_Wp + W_WS2 + 4096, tid);
        #pragma unroll
        for (int nt = 0; nt < 2; nt++) {
            int n0 = wid*16 + nt*8 + 2*q4;
            float2 bv = *(const float2*)&bs2[n0];
            float2 h0 = *(float2*)&Hs[row0*128 + n0];
            float2 h1 = *(float2*)&Hs[row1*128 + n0];
            *(float2*)&HDS[(size_t)(rowBase+row0)*128 + n0] =
                make_float2(c[nt][0]+bv.x+h0.x, c[nt][1]+bv.y+h0.y);
            *(float2*)&HDS[(size_t)(rowBase+row1)*128 + n0] =
                make_float2(c[nt][2]+bv.x+h1.x, c[nt][3]+bv.y+h1.y);
        }
    }

    // units 3..10: A/B[tau] = HB @ wi1[tau,half] (+bi1 for half 0)
    #pragma unroll 1
    for (int u = 0; u < 8; u++) {
        int tau = u >> 1, half = u & 1;
        float c[2][4] = {};
        const uint32_t* Wg = g_Wp + W_WI1 + u*8192;
        ug16(c, sm, smB, MA_WT, MA_HB, 68, 0,  Wg, tid);
        ug16(c, sm, smB, MA_WT, MA_HB, 68, 32, Wg + 4096, tid);
        uint32_t* ob = (uint32_t*)((half ? Bb : Ab) +
                        ((size_t)tau*ROWS + rowBase)*128);
        #pragma unroll
        for (int nt = 0; nt < 2; nt++) {
            int n0 = wid*16 + nt*8 + 2*q4;
            float2 bv = half ? make_float2(0.f,0.f)
                             : *(const float2*)&bi1[tau*128 + n0];
            ob[row0*64 + (n0>>1)] = pk2(c[nt][0]+bv.x, c[nt][1]+bv.y);
            ob[row1*64 + (n0>>1)] = pk2(c[nt][2]+bv.x, c[nt][3]+bv.y);
        }
    }
}

// ---------------- HMMA fused inter kernel (N-split, 2 CTA/SM) ---------------
// Block (b, tau, z): z selects 64-col half of the output. Warp layout:
// warp_m = wid>>2 (sender parity), warp_n = wid&3 (16 cols each, nt in {0,1}).
#define WSTR 68
#define SM_AS   0                       // 64*68*4 = 17408
#define SM_BS   17408
#define SM_W2   34816                   // 64*68*4 = 17408
#define SM_WM   52224                   // 16384
#define SM_BI2  68608                   // 256
#define SM_TOT  68864

__global__ void __launch_bounds__(256, 2) inter_hmma_kernel(
    const __nv_bfloat16* __restrict__ gAb, const __nv_bfloat16* __restrict__ gBb,
    const float* __restrict__ bi2,
    const float* __restrict__ ep, const float* __restrict__ et,
    __nv_bfloat16* __restrict__ gSb, float* __restrict__ gW)
{
    extern __shared__ char sm[];
    uint32_t* Asm  = (uint32_t*)(sm + SM_AS);
    uint32_t* Bsm  = (uint32_t*)(sm + SM_BS);
    uint32_t* W2s  = (uint32_t*)(sm + SM_W2);
    float* Wmat = (float*)(sm + SM_WM);
    float* bi2s = (float*)(sm + SM_BI2);

    int tid = threadIdx.x, lane = tid & 31, wid = tid >> 5;
    int b = blockIdx.x, tau = blockIdx.y, z = blockIdx.z;
    int g = lane >> 2, q4 = lane & 3;
    int warp_m = wid >> 2;
    int warp_n = wid & 3;
    int lA_row = lane & 15, lA_kw = (lane >> 4) << 2;
    int lB_row = (lane & 7) + ((lane >> 4) << 3);
    int lB_kw  = ((lane >> 3) & 1) << 2;
    uint32_t BsB = s2u(sm) + SM_BS, W2B = s2u(sm) + SM_W2;

    const uint4* Ag = (const uint4*)(gAb + ((size_t)tau*ROWS + b*64)*128);
    const uint4* Bg = (const uint4*)(gBb + ((size_t)tau*ROWS + b*64)*128);
    #pragma unroll
    for (int l = 0; l < 4; l++) {
        int v = tid + l*256;
        int row = v >> 4, wq = v & 15;
        *(uint4*)&Asm[row*WSTR + wq*4] = Ag[row*16 + wq];
        *(uint4*)&Bsm[row*WSTR + wq*4] = Bg[row*16 + wq];
    }
    // W2 half: prepped [tau][n:128][w:64]; rows z*64..z*64+63
    {
        const uint4* src = (const uint4*)(g_Wp + W_WI2F + tau*8192 + z*4096);
        #pragma unroll
        for (int l = 0; l < 4; l++) {
            int u = tid + l*256;         // uint4 index (1024)
            int n = u >> 4, q = u & 15;
            *(uint4*)&W2s[n*WSTR + q*4] = src[u];
        }
    }
    const size_t ebase = (size_t)b*64*64;
    #pragma unroll
    for (int l = 0; l < 16; l++) {
        int q = tid + l*256;
        Wmat[q] = ep[ebase + q] * et[(ebase + q)*4 + tau];
    }
    if (tid < 64) bi2s[tid] = bi2[tau*128 + z*64 + tid];
    __syncthreads();

    if (z == 0 && tid < 64) {
        float s = 0.f;
        #pragma unroll 8
        for (int i = 0; i < 64; i++) s += Wmat[i*64 + tid];
        gW[(size_t)(b*64 + tid)*4 + tau] = s;
    }

    float bi2v[2][2];
    #pragma unroll
    for (int nt = 0; nt < 2; nt++) {
        int n0 = warp_n*16 + nt*8 + 2*q4;
        bi2v[nt][0] = bi2s[n0];
        bi2v[nt][1] = bi2s[n0 + 1];
    }

    float S[4][2][4] = {};

    for (int it = 0; it < 32; it++) {
        int i = 2*it + warp_m;
        float c[4][2][4] = {};
        #pragma unroll
        for (int kk = 0; kk < 8; kk++) {
            uint32_t aw0 = Asm[i*WSTR + kk*8 + q4];
            uint32_t aw1 = Asm[i*WSTR + kk*8 + 4 + q4];
            uint32_t wf[4];
            ldmx4(wf, W2B + ((warp_n*16 + lB_row)*WSTR + kk*8 + lB_kw)*4);
            #pragma unroll
            for (int mt = 0; mt < 4; mt++) {
                uint32_t xb[4], x[4];
                ldmx4(xb, BsB + ((mt*16 + lA_row)*WSTR + kk*8 + lA_kw)*4);
                x[0] = addrelu2(xb[0], aw0);
                x[1] = addrelu2(xb[1], aw0);
                x[2] = addrelu2(xb[2], aw1);
                x[3] = addrelu2(xb[3], aw1);
                mma16816(c[mt][0], x, wf[0], wf[1]);
                mma16816(c[mt][1], x, wf[2], wf[3]);
            }
        }
        #pragma unroll
        for (int mt = 0; mt < 4; mt++) {
            float w0 = Wmat[i*64 + mt*16 + g];
            float w1 = Wmat[i*64 + mt*16 + g + 8];
            #pragma unroll
            for (int nt = 0; nt < 2; nt++) {
                S[mt][nt][0] += w0*fmaxf(c[mt][nt][0] + bi2v[nt][0], 0.f);
                S[mt][nt][1] += w0*fmaxf(c[mt][nt][1] + bi2v[nt][1], 0.f);
                S[mt][nt][2] += w1*fmaxf(c[mt][nt][2] + bi2v[nt][0], 0.f);
                S[mt][nt][3] += w1*fmaxf(c[mt][nt][3] + bi2v[nt][1], 0.f);
            }
        }
    }

    // combine sender parities (reuse W2 area: 64 rows x 68 floats)
    float* Sout = (float*)(sm + SM_W2);
    __syncthreads();
    if (warp_m == 0) {
        #pragma unroll
        for (int mt = 0; mt < 4; mt++) {
            int j = mt*16 + g;
            #pragma unroll
            for (int nt = 0; nt < 2; nt++) {
                int n = warp_n*16 + nt*8 + 2*q4;
                *(float2*)&Sout[j*68 + n] = make_float2(S[mt][nt][0], S[mt][nt][1]);
                *(float2*)&Sout[(j+8)*68 + n] = make_float2(S[mt][nt][2], S[mt][nt][3]);
            }
        }
    }
    __syncthreads();
    if (warp_m == 1) {
        #pragma unroll
        for (int mt = 0; mt < 4; mt++) {
            int j = mt*16 + g;
            #pragma unroll
            for (int nt = 0; nt < 2; nt++) {
                int n = warp_n*16 + nt*8 + 2*q4;
                float2 v0 = *(float2*)&Sout[j*68 + n];
                v0.x += S[mt][nt][0]; v0.y += S[mt][nt][1];
                *(float2*)&Sout[j*68 + n] = v0;
                float2 v1 = *(float2*)&Sout[(j+8)*68 + n];
                v1.x += S[mt][nt][2]; v1.y += S[mt][nt][3];
                *(float2*)&Sout[(j+8)*68 + n] = v1;
            }
        }
    }
    __syncthreads();
    for (int q = tid; q < 1024; q += 256) {
        int j = q >> 4, w = q & 15;
        float4 v = *(float4*)&Sout[j*68 + w*4];
        uint2 u = make_uint2(pk2(v.x, v.y), pk2(v.z, v.w));
        *(uint2*)&gSb[(size_t)(b*64 + j)*512 + tau*128 + z*64 + w*4] = u;
    }
}

// ---------------- megaB: wi3 GEMM + LN256 + update MLP (16-row tiles) -------
#define MB_AS   0                       // 16*36*4 = 2304
#define MB_DI   2304                    // 16*132*4 = 8448
#define MB_CN   10752                   // 8448
#define MB_T1   19200                   // 16*68*4 = 4352
#define MB_WT   23552                   // 18432
#define MB_TOT  41984

__global__ void __launch_bounds__(256) megaB_kernel(
    const __nv_bfloat16* __restrict__ Sb, const float* __restrict__ Wq,
    const float* __restrict__ bi3, const float* __restrict__ HDS,
    const float* __restrict__ lu_g, const float* __restrict__ lu_b,
    const float* __restrict__ bu1, const float* __restrict__ bu2,
    const float* __restrict__ hResid, float* __restrict__ hOut)
{
    extern __shared__ char sm[];
    uint32_t* As = (uint32_t*)(sm + MB_AS);
    float*    DIs = (float*)(sm + MB_DI);
    uint32_t* CN = (uint32_t*)(sm + MB_CN);
    uint32_t* T1 = (uint32_t*)(sm + MB_T1);
    uint32_t smB = s2u(sm);
    int tid = threadIdx.x, lane = tid & 31, wid = tid >> 5;
    int rowBase = blockIdx.x * 16;
    int g = lane >> 2, q4 = lane & 3;
    int row0 = g, row1 = g + 8;

    // unit 1: DI = Sb @ wi3 (K=512) + wsum.bi3  -> smem fp32
    {
        float c[2][4] = {};
        for (int c8 = 0; c8 < 8; c8++) {
            if (tid < 128) {
                int lr = tid >> 3, uu = tid & 7;
                *(uint4*)&As[lr*36 + uu*4] =
                    *(const uint4*)&((const uint4*)Sb)[(size_t)(rowBase+lr)*64 + c8*8 + uu];
            }
            ug16(c, sm, smB, MB_WT, MB_AS, 36, 0, g_Wp + W_WI3 + c8*4096, tid);
        }
        float4 wa = *(const float4*)&Wq[(size_t)(rowBase+row0)*4];
        float4 wb = *(const float4*)&Wq[(size_t)(rowBase+row1)*4];
        #pragma unroll
        for (int nt = 0; nt < 2; nt++) {
            int n0 = wid*16 + nt*8 + 2*q4;
            float2 v0 = make_float2(c[nt][0], c[nt][1]);
            float2 v1 = make_float2(c[nt][2], c[nt][3]);
            #pragma unroll
            for (int t = 0; t < 4; t++) {
                float wta = (t==0)?wa.x:(t==1)?wa.y:(t==2)?wa.z:wa.w;
                float wtb = (t==0)?wb.x:(t==1)?wb.y:(t==2)?wb.z:wb.w;
                float2 rb = *(const float2*)&bi3[t*128 + n0];
                v0.x += wta*rb.x; v0.y += wta*rb.y;
                v1.x += wtb*rb.x; v1.y += wtb*rb.y;
            }
            *(float2*)&DIs[row0*132 + n0] = v0;
            *(float2*)&DIs[row1*132 + n0] = v1;
        }
    }
    __syncthreads();

    // LN256 over [HDS row (gmem), DIs row (smem)] -> CN bf16
    {
        float4 g0 = ((const float4*)lu_g)[lane];
        float4 g1 = ((const float4*)lu_g)[32 + lane];
        float4 c0 = ((const float4*)lu_b)[lane];
        float4 c1 = ((const float4*)lu_b)[32 + lane];
        #pragma unroll
        for (int p = 0; p < 2; p++) {
            int r = wid + p*8;
            float4 v0 = *(const float4*)&HDS[(size_t)(rowBase+r)*128 + lane*4];
            float4 v1 = *(float4*)&DIs[r*132 + lane*4];
            float s = v0.x+v0.y+v0.z+v0.w + v1.x+v1.y+v1.z+v1.w;
            #pragma unroll
            for (int o = 16; o; o >>= 1) s += __shfl_xor_sync(0xffffffffu, s, o);
            float mu = s * (1.0f/256.0f);
            float a0=v0.x-mu, a1=v0.y-mu, a2=v0.z-mu, a3=v0.w-mu;
            float b0=v1.x-mu, b1=v1.y-mu, b2=v1.z-mu, b3=v1.w-mu;
            float q = a0*a0+a1*a1+a2*a2+a3*a3 + b0*b0+b1*b1+b2*b2+b3*b3;
            #pragma unroll
            for (int o = 16; o; o >>= 1) q += __shfl_xor_sync(0xffffffffu, q, o);
            float rs = rsqrtf(q * (1.0f/256.0f) + EPSLN);
            CN[r*132 + lane*2]        = pk2(a0*rs*g0.x + c0.x, a1*rs*g0.y + c0.y);
            CN[r*132 + lane*2 + 1]    = pk2(a2*rs*g0.z + c0.z, a3*rs*g0.w + c0.w);
            CN[r*132 + 64 + lane*2]   = pk2(b0*rs*g1.x + c1.x, b1*rs*g1.y + c1.y);
            CN[r*132 + 64 + lane*2+1] = pk2(b2*rs*g1.z + c1.z, b3*rs*g1.w + c1.w);
        }
    }

    // unit 2: T1 = relu(CN @ wu1 + bu1)  (K=256)
    {
        float c[2][4] = {};
        for (int ch = 0; ch < 4; ch++)
            ug16(c, sm, smB, MB_WT, MB_CN, 132, ch*32,
                 g_Wp + W_WU1 + ch*4096, tid);
        #pragma unroll
        for (int nt = 0; nt < 2; nt++) {
            int n0 = wid*16 + nt*8 + 2*q4;
            float2 bv = *(const float2*)&bu1[n0];
            T1[row0*68 + (n0>>1)] =
                pk2(fmaxf(c[nt][0]+bv.x,0.f), fmaxf(c[nt][1]+bv.y,0.f));
            T1[row1*68 + (n0>>1)] =
                pk2(fmaxf(c[nt][2]+bv.x,0.f), fmaxf(c[nt][3]+bv.y,0.f));
        }
    }

    // unit 3: hOut = hResid + T1 @ wu2 + bu2
    {
        float c[2][4] = {};
        ug16(c, sm, smB, MB_WT, MB_T1, 68, 0,  g_Wp + W_WU2, tid);
        ug16(c, sm, smB, MB_WT, MB_T1, 68, 32, g_Wp + W_WU2 + 4096, tid);
        #pragma unroll
        for (int nt = 0; nt < 2; nt++) {
            int n0 = wid*16 + nt*8 + 2*q4;
            float2 bv = *(const float2*)&bu2[n0];
            float2 h0 = *(const float2*)&hResid[(size_t)(rowBase+row0)*128 + n0];
            float2 h1 = *(const float2*)&hResid[(size_t)(rowBase+row1)*128 + n0];
            *(float2*)&hOut[(size_t)(rowBase+row0)*128 + n0] =
                make_float2(c[nt][0]+bv.x+h0.x, c[nt][1]+bv.y+h0.y);
            *(float2*)&hOut[(size_t)(rowBase+row1)*128 + n0] =
                make_float2(c[nt][2]+bv.x+h1.x, c[nt][3]+bv.y+h1.y);
        }
    }
}

// ---------------- host orchestration ----------------
extern "C" void kernel_launch(void* const* d_in, const int* in_sizes, int n_in,
                              void* d_out, int out_size)
{
    const float* slots = (const float*)d_in[0];
    const float* ep    = (const float*)d_in[1];
    const float* et    = (const float*)d_in[2];
    const float* ls_g  = (const float*)d_in[3];
    const float* ls_b  = (const float*)d_in[4];
    const float* ws1   = (const float*)d_in[5];
    const float* bs1   = (const float*)d_in[6];
    const float* ws2   = (const float*)d_in[7];
    const float* bs2   = (const float*)d_in[8];
    const float* wi1   = (const float*)d_in[9];
    const float* bi1   = (const float*)d_in[10];
    const float* wi2   = (const float*)d_in[11];
    const float* bi2   = (const float*)d_in[12];
    const float* wi3   = (const float*)d_in[13];
    const float* bi3   = (const float*)d_in[14];
    const float* lu_g  = (const float*)d_in[15];
    const float* lu_b  = (const float*)d_in[16];
    const float* wu1   = (const float*)d_in[17];
    const float* bu1   = (const float*)d_in[18];
    const float* wu2   = (const float*)d_in[19];
    const float* bu2   = (const float*)d_in[20];
    float* out = (float*)d_out;

    float *HDS, *H, *W;
    __nv_bfloat16 *Ab, *Bb, *Sb;
    cudaGetSymbolAddress((void**)&HDS, g_HDS);
    cudaGetSymbolAddress((void**)&H,   g_H);
    cudaGetSymbolAddress((void**)&W,   g_W);
    cudaGetSymbolAddress((void**)&Ab,  g_Ab);
    cudaGetSymbolAddress((void**)&Bb,  g_Bb);
    cudaGetSymbolAddress((void**)&Sb,  g_Sb);

    cudaFuncSetAttribute(megaA_kernel,
        cudaFuncAttributeMaxDynamicSharedMemorySize, MA_TOT);
    cudaFuncSetAttribute(megaB_kernel,
        cudaFuncAttributeMaxDynamicSharedMemorySize, MB_TOT);
    cudaFuncSetAttribute(inter_hmma_kernel,
        cudaFuncAttributeMaxDynamicSharedMemorySize, SM_TOT);

    prep_weights<<<(W_TOTAL+255)/256, 256>>>(ws1, ws2, wu2, wi3, wu1, wi1, wi2);

    const float* h = slots;
    for (int it = 0; it < 2; it++) {
        megaA_kernel<<<256, 256, MA_TOT>>>(h, ls_g, ls_b, bs1, bs2, bi1,
                                           HDS, Ab, Bb);
        inter_hmma_kernel<<<dim3(BB, TT, 2), 256, SM_TOT>>>(
            Ab, Bb, bi2, ep, et, Sb, W);
        float* hnew = (it == 0) ? H : out;
        megaB_kernel<<<256, 256, MB_TOT>>>(Sb, W, bi3, HDS, lu_g, lu_b,
                                           bu1, bu2, h, hnew);
        h = H;
    }
}

// round 7
// speedup vs baseline: 1.1782x; 1.1782x over previous
#include <cuda_runtime.h>
#include <cuda_bf16.h>
#include <cstdint>

// Problem constants
#define BB 64
#define KK 64
#define DD 128
#define HH 128
#define TT 4
#define ROWS (BB*KK)        // 4096
#define EPSLN 1e-5f

// ---------------- scratch (no allocations allowed) ----------------
__device__ float g_HDS[ROWS*DD];
__device__ float g_H  [ROWS*DD];
__device__ float g_W  [ROWS*TT];                 // [row][tau]
__device__ __nv_bfloat16 g_Ab [TT*ROWS*HH];
__device__ __nv_bfloat16 g_Bb [TT*ROWS*HH];
__device__ __nv_bfloat16 g_Sb [ROWS*TT*HH];      // [row][tau*128+n]

// prepped weights: bf16, [n][k-pair] chunked (4096 words per 64-k chunk)
#define W_WS1   0
#define W_WS2   8192
#define W_WU2   16384
#define W_WI3   24576
#define W_WU1   57344
#define W_WI1   73728
#define W_WI2F  139264
#define W_TOTAL 172032
__device__ __align__(16) uint32_t g_Wp[W_TOTAL];

// ---------------- helpers ----------------
__device__ __forceinline__ uint32_t pk2(float lo, float hi){
    __nv_bfloat162 v = __floats2bfloat162_rn(lo, hi);
    return *(uint32_t*)&v;
}
__device__ __forceinline__ uint32_t addrelu2(uint32_t a, uint32_t b){
    __nv_bfloat162 av = *(__nv_bfloat162*)&a;
    __nv_bfloat162 bv = *(__nv_bfloat162*)&b;
    __nv_bfloat162 z  = __float2bfloat162_rn(0.f);
    __nv_bfloat162 r  = __hmax2(__hadd2(av, bv), z);
    return *(uint32_t*)&r;
}
__device__ __forceinline__ void mma16816(float c[4], const uint32_t a[4],
                                         uint32_t b0, uint32_t b1){
    asm volatile(
        "mma.sync.aligned.m16n8k16.row.col.f32.bf16.bf16.f32 "
        "{%0,%1,%2,%3}, {%4,%5,%6,%7}, {%8,%9}, {%0,%1,%2,%3};\n"
        : "+f"(c[0]), "+f"(c[1]), "+f"(c[2]), "+f"(c[3])
        : "r"(a[0]), "r"(a[1]), "r"(a[2]), "r"(a[3]), "r"(b0), "r"(b1));
}
__device__ __forceinline__ void ldmx4(uint32_t r[4], uint32_t a){
    asm volatile("ldmatrix.sync.aligned.m8n8.x4.shared.b16 {%0,%1,%2,%3}, [%4];"
        : "=r"(r[0]), "=r"(r[1]), "=r"(r[2]), "=r"(r[3]) : "r"(a));
}
__device__ __forceinline__ uint32_t s2u(const void* p){
    return (uint32_t)__cvta_generic_to_shared((void*)p);
}

// ---------------- weight prep: fp32 [K][128] -> bf16 [chunk][n][kw] ---------
__global__ void __launch_bounds__(256) prep_weights(
    const float* __restrict__ ws1, const float* __restrict__ ws2,
    const float* __restrict__ wu2, const float* __restrict__ wi3,
    const float* __restrict__ wu1, const float* __restrict__ wi1,
    const float* __restrict__ wi2)
{
    int idx = blockIdx.x*256 + threadIdx.x;
    if (idx >= W_TOTAL) return;
    const float* src;
    int local;
    if (idx < W_WS2)       { src = ws1; local = idx - W_WS1; }
    else if (idx < W_WU2)  { src = ws2; local = idx - W_WS2; }
    else if (idx < W_WI3)  { src = wu2; local = idx - W_WU2; }
    else if (idx < W_WU1)  { src = wi3; local = idx - W_WI3; }
    else if (idx < W_WI1)  { src = wu1; local = idx - W_WU1; }
    else if (idx < W_WI2F) {
        int l = idx - W_WI1;
        int tau = l >> 14;               // 16384 words per tau
        src = wi1 + (size_t)tau*256*128;
        local = l & 16383;
    } else {
        // wi2 flat: [tau][n:128][w:64]
        int l = idx - W_WI2F;
        int tau = l >> 13;               // 8192 per tau
        int r = l & 8191;
        int n = r >> 6, w = r & 63;
        const float* s = wi2 + (size_t)tau*16384;
        g_Wp[idx] = pk2(s[(size_t)(2*w)*128 + n], s[(size_t)(2*w+1)*128 + n]);
        return;
    }
    int c = local >> 12;                 // 4096 words per chunk
    int r = local & 4095;
    int n = r >> 5, w = r & 31;
    int k = c*64 + 2*w;
    g_Wp[idx] = pk2(src[(size_t)k*128 + n], src[(size_t)(k+1)*128 + n]);
}

// ---------------- unit GEMM chunk (32 rows x 128 n x 64 k) ------------------
#define GSTR 36

__device__ __forceinline__ void ug_chunk(
    float (&c)[4][4], char* sm, uint32_t smB, int wtOff,
    int aOff, int astr, int aChunkOff,
    const uint32_t* __restrict__ WgChunk, int tid)
{
    uint32_t* Wt = (uint32_t*)(sm + wtOff);
    #pragma unroll
    for (int l = 0; l < 4; l++) {
        int u = tid + l*256;             // uint4 index (1024)
        int n = u >> 3, w0 = (u & 7) * 4;
        *(uint4*)&Wt[n*GSTR + w0] = *(const uint4*)&WgChunk[u*4];
    }
    __syncthreads();
    int lane = tid & 31, wid = tid >> 5;
    int warp_m = wid >> 2, warp_n = wid & 3;
    int lA_row = lane & 15, lA_kw = (lane >> 4) << 2;
    int lB_row = (lane & 7) + ((lane >> 4) << 3);
    int lB_kw  = ((lane >> 3) & 1) << 2;
    uint32_t AsB = smB + aOff, WtB = smB + (uint32_t)wtOff;
    #pragma unroll
    for (int kk = 0; kk < 4; kk++) {
        uint32_t wf0[4], wf1[4], a[4];
        ldmx4(wf0, WtB + ((warp_n*32 + lB_row)*GSTR + kk*8 + lB_kw)*4);
        ldmx4(wf1, WtB + ((warp_n*32 + 16 + lB_row)*GSTR + kk*8 + lB_kw)*4);
        ldmx4(a, AsB + ((warp_m*16 + lA_row)*astr + aChunkOff + kk*8 + lA_kw)*4);
        mma16816(c[0], a, wf0[0], wf0[1]);
        mma16816(c[1], a, wf0[2], wf0[3]);
        mma16816(c[2], a, wf1[0], wf1[1]);
        mma16816(c[3], a, wf1[2], wf1[3]);
    }
    __syncthreads();
}

// ---------------- megaA: LN128 + self-MLP + wi1 (32-row tiles, grid 128) ----
#define MA_HS   0                       // 32*128 f32 = 16384
#define MA_XN   16384                   // 32*68*4 = 8704
#define MA_HB   25088                   // 8704
#define MA_T1   33792                   // 8704
#define MA_WT   42496                   // 128*36*4 = 18432
#define MA_TOT  60928

__global__ void __launch_bounds__(256) megaA_kernel(
    const float* __restrict__ h,
    const float* __restrict__ ls_g, const float* __restrict__ ls_b,
    const float* __restrict__ bs1, const float* __restrict__ bs2,
    const float* __restrict__ bi1,
    float* __restrict__ HDS, __nv_bfloat16* __restrict__ Ab,
    __nv_bfloat16* __restrict__ Bb)
{
    extern __shared__ char sm[];
    float* Hs = (float*)(sm + MA_HS);
    uint32_t* XN = (uint32_t*)(sm + MA_XN);
    uint32_t* HB = (uint32_t*)(sm + MA_HB);
    uint32_t* T1 = (uint32_t*)(sm + MA_T1);
    uint32_t smB = s2u(sm);
    int tid = threadIdx.x, lane = tid & 31, wid = tid >> 5;
    int rowBase = blockIdx.x * 32;
    int g = lane >> 2, q4 = lane & 3;
    int warp_m = wid >> 2, warp_n = wid & 3;
    int row0 = warp_m*16 + g, row1 = row0 + 8;

    #pragma unroll
    for (int l = 0; l < 4; l++) {
        int u = tid + l*256;
        int r = u >> 5, q = u & 31;
        *(float4*)&Hs[r*128 + q*4] =
            *(const float4*)&h[(size_t)(rowBase+r)*128 + q*4];
    }
    __syncthreads();

    {
        float4 gg = ((const float4*)ls_g)[lane];
        float4 bb = ((const float4*)ls_b)[lane];
        #pragma unroll
        for (int p = 0; p < 4; p++) {
            int r = wid + p*8;
            float4 v = *(float4*)&Hs[r*128 + lane*4];
            float s = v.x + v.y + v.z + v.w;
            #pragma unroll
            for (int o = 16; o; o >>= 1) s += __shfl_xor_sync(0xffffffffu, s, o);
            float mu = s * (1.0f/128.0f);
            float dx = v.x-mu, dy = v.y-mu, dz = v.z-mu, dw = v.w-mu;
            float q = dx*dx + dy*dy + dz*dz + dw*dw;
            #pragma unroll
            for (int o = 16; o; o >>= 1) q += __shfl_xor_sync(0xffffffffu, q, o);
            float rs = rsqrtf(q * (1.0f/128.0f) + EPSLN);
            XN[r*68 + lane*2]   = pk2(dx*rs*gg.x + bb.x, dy*rs*gg.y + bb.y);
            XN[r*68 + lane*2+1] = pk2(dz*rs*gg.z + bb.z, dw*rs*gg.w + bb.w);
            HB[r*68 + lane*2]   = pk2(v.x, v.y);
            HB[r*68 + lane*2+1] = pk2(v.z, v.w);
        }
    }
    __syncthreads();

    {
        float c[4][4] = {};
        ug_chunk(c, sm, smB, MA_WT, MA_XN, 68, 0,  g_Wp + W_WS1, tid);
        ug_chunk(c, sm, smB, MA_WT, MA_XN, 68, 32, g_Wp + W_WS1 + 4096, tid);
        #pragma unroll
        for (int nt = 0; nt < 4; nt++) {
            int n0 = warp_n*32 + nt*8 + 2*q4;
            float2 bv = *(const float2*)&bs1[n0];
            T1[row0*68 + (n0>>1)] =
                pk2(fmaxf(c[nt][0]+bv.x,0.f), fmaxf(c[nt][1]+bv.y,0.f));
            T1[row1*68 + (n0>>1)] =
                pk2(fmaxf(c[nt][2]+bv.x,0.f), fmaxf(c[nt][3]+bv.y,0.f));
        }
    }

    {
        float c[4][4] = {};
        ug_chunk(c, sm, smB, MA_WT, MA_T1, 68, 0,  g_Wp + W_WS2, tid);
        ug_chunk(c, sm, smB, MA_WT, MA_T1, 68, 32, g_Wp + W_WS2 + 4096, tid);
        #pragma unroll
        for (int nt = 0; nt < 4; nt++) {
            int n0 = warp_n*32 + nt*8 + 2*q4;
            float2 bv = *(const float2*)&bs2[n0];
            float2 h0 = *(float2*)&Hs[row0*128 + n0];
            float2 h1 = *(float2*)&Hs[row1*128 + n0];
            *(float2*)&HDS[(size_t)(rowBase+row0)*128 + n0] =
                make_float2(c[nt][0]+bv.x+h0.x, c[nt][1]+bv.y+h0.y);
            *(float2*)&HDS[(size_t)(rowBase+row1)*128 + n0] =
                make_float2(c[nt][2]+bv.x+h1.x, c[nt][3]+bv.y+h1.y);
        }
    }

    #pragma unroll 1
    for (int u = 0; u < 8; u++) {
        int tau = u >> 1, half = u & 1;
        float c[4][4] = {};
        const uint32_t* Wg = g_Wp + W_WI1 + u*8192;
        ug_chunk(c, sm, smB, MA_WT, MA_HB, 68, 0,  Wg, tid);
        ug_chunk(c, sm, smB, MA_WT, MA_HB, 68, 32, Wg + 4096, tid);
        uint32_t* ob = (uint32_t*)((half ? Bb : Ab) +
                        ((size_t)tau*ROWS + rowBase)*128);
        #pragma unroll
        for (int nt = 0; nt < 4; nt++) {
            int n0 = warp_n*32 + nt*8 + 2*q4;
            float2 bv = half ? make_float2(0.f,0.f)
                             : *(const float2*)&bi1[tau*128 + n0];
            ob[row0*64 + (n0>>1)] = pk2(c[nt][0]+bv.x, c[nt][1]+bv.y);
            ob[row1*64 + (n0>>1)] = pk2(c[nt][2]+bv.x, c[nt][3]+bv.y);
        }
    }
}

// ---------------- HMMA fused inter kernel (M-split over receivers) ----------
// Block (b, tau, z): z selects j in [32z, 32z+32). All 128 cols per block.
// Warps: warp_m = sender parity, warp_n = column quarter (32 cols).
// Per iter: i = 2it + warp_m; warp covers 32 j rows (mt in {0,1}).
#define WSTR 68
#define SM_AS   0                       // A: 64*68*4 = 17408
#define SM_BS   17408                   // B half: 32*68*4 = 8704
#define SM_W2   26112                   // W2: 128*68*4 = 34816
#define SM_WM   60928                   // Wmat: 64*32*4 = 8192
#define SM_BI2  69120                   // 512
#define SM_TOT  69632

__global__ void __launch_bounds__(256, 2) inter_hmma_kernel(
    const __nv_bfloat16* __restrict__ gAb, const __nv_bfloat16* __restrict__ gBb,
    const float* __restrict__ bi2,
    const float* __restrict__ ep, const float* __restrict__ et,
    __nv_bfloat16* __restrict__ gSb, float* __restrict__ gW)
{
    extern __shared__ char sm[];
    uint32_t* Asm  = (uint32_t*)(sm + SM_AS);
    uint32_t* Bsm  = (uint32_t*)(sm + SM_BS);
    uint32_t* W2s  = (uint32_t*)(sm + SM_W2);
    float* Wmat = (float*)(sm + SM_WM);    // [i:64][jj:32]
    float* bi2s = (float*)(sm + SM_BI2);

    int tid = threadIdx.x, lane = tid & 31, wid = tid >> 5;
    int b = blockIdx.x, tau = blockIdx.y, z = blockIdx.z;
    int g = lane >> 2, q4 = lane & 3;
    int warp_m = wid >> 2;
    int warp_n = wid & 3;
    int lA_row = lane & 15, lA_kw = (lane >> 4) << 2;
    int lB_row = (lane & 7) + ((lane >> 4) << 3);
    int lB_kw  = ((lane >> 3) & 1) << 2;
    uint32_t BsB = s2u(sm) + SM_BS, W2B = s2u(sm) + SM_W2;

    // A: all 64 senders; B: 32 receiver rows for this z
    const uint4* Ag = (const uint4*)(gAb + ((size_t)tau*ROWS + b*64)*128);
    const uint4* Bg = (const uint4*)(gBb + ((size_t)tau*ROWS + b*64 + z*32)*128);
    #pragma unroll
    for (int l = 0; l < 4; l++) {
        int v = tid + l*256;
        int row = v >> 4, wq = v & 15;
        *(uint4*)&Asm[row*WSTR + wq*4] = Ag[row*16 + wq];
    }
    #pragma unroll
    for (int l = 0; l < 2; l++) {
        int v = tid + l*256;
        int row = v >> 4, wq = v & 15;
        *(uint4*)&Bsm[row*WSTR + wq*4] = Bg[row*16 + wq];
    }
    // W2 full 128 rows from prepped layout
    {
        const uint4* src = (const uint4*)(g_Wp + W_WI2F + tau*8192);
        #pragma unroll
        for (int l = 0; l < 8; l++) {
            int u = tid + l*256;
            int n = u >> 4, q = u & 15;
            *(uint4*)&W2s[n*WSTR + q*4] = src[u];
        }
    }
    // pair weights for this j-half: Wmat[i][jj] = ep*et
    const size_t ebase = (size_t)b*64*64 + z*32;
    #pragma unroll
    for (int l = 0; l < 8; l++) {
        int q = tid + l*256;
        int i = q >> 5, jj = q & 31;
        size_t idx = ebase + (size_t)i*64 + jj;
        Wmat[q] = ep[idx] * et[idx*4 + tau];
    }
    if (tid < 128) bi2s[tid] = bi2[tau*128 + tid];
    __syncthreads();

    // wsum for this block's 32 receivers
    if (tid < 32) {
        float s = 0.f;
        #pragma unroll 8
        for (int i = 0; i < 64; i++) s += Wmat[i*32 + tid];
        gW[(size_t)(b*64 + z*32 + tid)*4 + tau] = s;
    }

    float bi2v[4][2];
    #pragma unroll
    for (int nt = 0; nt < 4; nt++) {
        int n0 = warp_n*32 + nt*8 + 2*q4;
        bi2v[nt][0] = bi2s[n0];
        bi2v[nt][1] = bi2s[n0 + 1];
    }

    float S[2][4][4] = {};

    for (int it = 0; it < 32; it++) {
        int i = 2*it + warp_m;
        float c[2][4][4] = {};
        #pragma unroll
        for (int kk = 0; kk < 8; kk++) {
            uint32_t aw0 = Asm[i*WSTR + kk*8 + q4];
            uint32_t aw1 = Asm[i*WSTR + kk*8 + 4 + q4];
            uint32_t wf0[4], wf1[4];
            ldmx4(wf0, W2B + ((warp_n*32 + lB_row)*WSTR + kk*8 + lB_kw)*4);
            ldmx4(wf1, W2B + ((warp_n*32 + 16 + lB_row)*WSTR + kk*8 + lB_kw)*4);
            #pragma unroll
            for (int mt = 0; mt < 2; mt++) {
                uint32_t xb[4], x[4];
                ldmx4(xb, BsB + ((mt*16 + lA_row)*WSTR + kk*8 + lA_kw)*4);
                x[0] = addrelu2(xb[0], aw0);
                x[1] = addrelu2(xb[1], aw0);
                x[2] = addrelu2(xb[2], aw1);
                x[3] = addrelu2(xb[3], aw1);
                mma16816(c[mt][0], x, wf0[0], wf0[1]);
                mma16816(c[mt][1], x, wf0[2], wf0[3]);
                mma16816(c[mt][2], x, wf1[0], wf1[1]);
                mma16816(c[mt][3], x, wf1[2], wf1[3]);
            }
        }
        #pragma unroll
        for (int mt = 0; mt < 2; mt++) {
            float w0 = Wmat[i*32 + mt*16 + g];
            float w1 = Wmat[i*32 + mt*16 + g + 8];
            #pragma unroll
            for (int nt = 0; nt < 4; nt++) {
                S[mt][nt][0] += w0*fmaxf(c[mt][nt][0] + bi2v[nt][0], 0.f);
                S[mt][nt][1] += w0*fmaxf(c[mt][nt][1] + bi2v[nt][1], 0.f);
                S[mt][nt][2] += w1*fmaxf(c[mt][nt][2] + bi2v[nt][0], 0.f);
                S[mt][nt][3] += w1*fmaxf(c[mt][nt][3] + bi2v[nt][1], 0.f);
            }
        }
    }

    // combine sender parities via smem (reuse W2 area: 32 rows x 132 floats)
    float* Sout = (float*)(sm + SM_W2);
    __syncthreads();
    if (warp_m == 0) {
        #pragma unroll
        for (int mt = 0; mt < 2; mt++) {
            int j = mt*16 + g;
            #pragma unroll
            for (int nt = 0; nt < 4; nt++) {
                int n = warp_n*32 + nt*8 + 2*q4;
                *(float2*)&Sout[j*132 + n] = make_float2(S[mt][nt][0], S[mt][nt][1]);
                *(float2*)&Sout[(j+8)*132 + n] = make_float2(S[mt][nt][2], S[mt][nt][3]);
            }
        }
    }
    __syncthreads();
    if (warp_m == 1) {
        #pragma unroll
        for (int mt = 0; mt < 2; mt++) {
            int j = mt*16 + g;
            #pragma unroll
            for (int nt = 0; nt < 4; nt++) {
                int n = warp_n*32 + nt*8 + 2*q4;
                float2 v0 = *(float2*)&Sout[j*132 + n];
                v0.x += S[mt][nt][0]; v0.y += S[mt][nt][1];
                *(float2*)&Sout[j*132 + n] = v0;
                float2 v1 = *(float2*)&Sout[(j+8)*132 + n];
                v1.x += S[mt][nt][2]; v1.y += S[mt][nt][3];
                *(float2*)&Sout[(j+8)*132 + n] = v1;
            }
        }
    }
    __syncthreads();
    for (int q = tid; q < 1024; q += 256) {
        int j = q >> 5, w = q & 31;
        float4 v = *(float4*)&Sout[j*132 + w*4];
        uint2 u = make_uint2(pk2(v.x, v.y), pk2(v.z, v.w));
        *(uint2*)&gSb[(size_t)(b*64 + z*32 + j)*512 + tau*128 + w*4] = u;
    }
}

// ---------------- megaB: wi3 GEMM + LN256 + update MLP (32-row tiles) -------
#define MB_AS   0                       // 32*36*4 = 4608
#define MB_DI   4608                    // 32*132*4 = 16896
#define MB_CN   21504                   // 16896
#define MB_T1   38400                   // 32*68*4 = 8704
#define MB_WT   47104                   // 18432
#define MB_TOT  65536

__global__ void __launch_bounds__(256) megaB_kernel(
    const __nv_bfloat16* __restrict__ Sb, const float* __restrict__ Wq,
    const float* __restrict__ bi3, const float* __restrict__ HDS,
    const float* __restrict__ lu_g, const float* __restrict__ lu_b,
    const float* __restrict__ bu1, const float* __restrict__ bu2,
    const float* __restrict__ hResid, float* __restrict__ hOut)
{
    extern __shared__ char sm[];
    uint32_t* As = (uint32_t*)(sm + MB_AS);
    float*    DIs = (float*)(sm + MB_DI);
    uint32_t* CN = (uint32_t*)(sm + MB_CN);
    uint32_t* T1 = (uint32_t*)(sm + MB_T1);
    uint32_t smB = s2u(sm);
    int tid = threadIdx.x, lane = tid & 31, wid = tid >> 5;
    int rowBase = blockIdx.x * 32;
    int g = lane >> 2, q4 = lane & 3;
    int warp_m = wid >> 2, warp_n = wid & 3;
    int row0 = warp_m*16 + g, row1 = row0 + 8;

    {
        float c[4][4] = {};
        for (int c8 = 0; c8 < 8; c8++) {
            int lr = tid >> 3, uu = tid & 7;
            *(uint4*)&As[lr*36 + uu*4] =
                *(const uint4*)&((const uint4*)Sb)[(size_t)(rowBase+lr)*64 + c8*8 + uu];
            ug_chunk(c, sm, smB, MB_WT, MB_AS, 36, 0,
                     g_Wp + W_WI3 + c8*4096, tid);
        }
        float4 wa = *(const float4*)&Wq[(size_t)(rowBase+row0)*4];
        float4 wb = *(const float4*)&Wq[(size_t)(rowBase+row1)*4];
        #pragma unroll
        for (int nt = 0; nt < 4; nt++) {
            int n0 = warp_n*32 + nt*8 + 2*q4;
            float2 v0 = make_float2(c[nt][0], c[nt][1]);
            float2 v1 = make_float2(c[nt][2], c[nt][3]);
            #pragma unroll
            for (int t = 0; t < 4; t++) {
                float wta = (t==0)?wa.x:(t==1)?wa.y:(t==2)?wa.z:wa.w;
                float wtb = (t==0)?wb.x:(t==1)?wb.y:(t==2)?wb.z:wb.w;
                float2 rb = *(const float2*)&bi3[t*128 + n0];
                v0.x += wta*rb.x; v0.y += wta*rb.y;
                v1.x += wtb*rb.x; v1.y += wtb*rb.y;
            }
            *(float2*)&DIs[row0*132 + n0] = v0;
            *(float2*)&DIs[row1*132 + n0] = v1;
        }
    }
    __syncthreads();

    {
        float4 g0 = ((const float4*)lu_g)[lane];
        float4 g1 = ((const float4*)lu_g)[32 + lane];
        float4 c0 = ((const float4*)lu_b)[lane];
        float4 c1 = ((const float4*)lu_b)[32 + lane];
        #pragma unroll
        for (int p = 0; p < 4; p++) {
            int r = wid + p*8;
            float4 v0 = *(const float4*)&HDS[(size_t)(rowBase+r)*128 + lane*4];
            float4 v1 = *(float4*)&DIs[r*132 + lane*4];
            float s = v0.x+v0.y+v0.z+v0.w + v1.x+v1.y+v1.z+v1.w;
            #pragma unroll
            for (int o = 16; o; o >>= 1) s += __shfl_xor_sync(0xffffffffu, s, o);
            float mu = s * (1.0f/256.0f);
            float a0=v0.x-mu, a1=v0.y-mu, a2=v0.z-mu, a3=v0.w-mu;
            float b0=v1.x-mu, b1=v1.y-mu, b2=v1.z-mu, b3=v1.w-mu;
            float q = a0*a0+a1*a1+a2*a2+a3*a3 + b0*b0+b1*b1+b2*b2+b3*b3;
            #pragma unroll
            for (int o = 16; o; o >>= 1) q += __shfl_xor_sync(0xffffffffu, q, o);
            float rs = rsqrtf(q * (1.0f/256.0f) + EPSLN);
            CN[r*132 + lane*2]        = pk2(a0*rs*g0.x + c0.x, a1*rs*g0.y + c0.y);
            CN[r*132 + lane*2 + 1]    = pk2(a2*rs*g0.z + c0.z, a3*rs*g0.w + c0.w);
            CN[r*132 + 64 + lane*2]   = pk2(b0*rs*g1.x + c1.x, b1*rs*g1.y + c1.y);
            CN[r*132 + 64 + lane*2+1] = pk2(b2*rs*g1.z + c1.z, b3*rs*g1.w + c1.w);
        }
    }

    {
        float c[4][4] = {};
        for (int ch = 0; ch < 4; ch++)
            ug_chunk(c, sm, smB, MB_WT, MB_CN, 132, ch*32,
                     g_Wp + W_WU1 + ch*4096, tid);
        #pragma unroll
        for (int nt = 0; nt < 4; nt++) {
            int n0 = warp_n*32 + nt*8 + 2*q4;
            float2 bv = *(const float2*)&bu1[n0];
            T1[row0*68 + (n0>>1)] =
                pk2(fmaxf(c[nt][0]+bv.x,0.f), fmaxf(c[nt][1]+bv.y,0.f));
            T1[row1*68 + (n0>>1)] =
                pk2(fmaxf(c[nt][2]+bv.x,0.f), fmaxf(c[nt][3]+bv.y,0.f));
        }
    }

    {
        float c[4][4] = {};
        ug_chunk(c, sm, smB, MB_WT, MB_T1, 68, 0,  g_Wp + W_WU2, tid);
        ug_chunk(c, sm, smB, MB_WT, MB_T1, 68, 32, g_Wp + W_WU2 + 4096, tid);
        #pragma unroll
        for (int nt = 0; nt < 4; nt++) {
            int n0 = warp_n*32 + nt*8 + 2*q4;
            float2 bv = *(const float2*)&bu2[n0];
            float2 h0 = *(const float2*)&hResid[(size_t)(rowBase+row0)*128 + n0];
            float2 h1 = *(const float2*)&hResid[(size_t)(rowBase+row1)*128 + n0];
            *(float2*)&hOut[(size_t)(rowBase+row0)*128 + n0] =
                make_float2(c[nt][0]+bv.x+h0.x, c[nt][1]+bv.y+h0.y);
            *(float2*)&hOut[(size_t)(rowBase+row1)*128 + n0] =
                make_float2(c[nt][2]+bv.x+h1.x, c[nt][3]+bv.y+h1.y);
        }
    }
}

// ---------------- host orchestration ----------------
extern "C" void kernel_launch(void* const* d_in, const int* in_sizes, int n_in,
                              void* d_out, int out_size)
{
    const float* slots = (const float*)d_in[0];
    const float* ep    = (const float*)d_in[1];
    const float* et    = (const float*)d_in[2];
    const float* ls_g  = (const float*)d_in[3];
    const float* ls_b  = (const float*)d_in[4];
    const float* ws1   = (const float*)d_in[5];
    const float* bs1   = (const float*)d_in[6];
    const float* ws2   = (const float*)d_in[7];
    const float* bs2   = (const float*)d_in[8];
    const float* wi1   = (const float*)d_in[9];
    const float* bi1   = (const float*)d_in[10];
    const float* wi2   = (const float*)d_in[11];
    const float* bi2   = (const float*)d_in[12];
    const float* wi3   = (const float*)d_in[13];
    const float* bi3   = (const float*)d_in[14];
    const float* lu_g  = (const float*)d_in[15];
    const float* lu_b  = (const float*)d_in[16];
    const float* wu1   = (const float*)d_in[17];
    const float* bu1   = (const float*)d_in[18];
    const float* wu2   = (const float*)d_in[19];
    const float* bu2   = (const float*)d_in[20];
    float* out = (float*)d_out;

    float *HDS, *H, *W;
    __nv_bfloat16 *Ab, *Bb, *Sb;
    cudaGetSymbolAddress((void**)&HDS, g_HDS);
    cudaGetSymbolAddress((void**)&H,   g_H);
    cudaGetSymbolAddress((void**)&W,   g_W);
    cudaGetSymbolAddress((void**)&Ab,  g_Ab);
    cudaGetSymbolAddress((void**)&Bb,  g_Bb);
    cudaGetSymbolAddress((void**)&Sb,  g_Sb);

    cudaFuncSetAttribute(megaA_kernel,
        cudaFuncAttributeMaxDynamicSharedMemorySize, MA_TOT);
    cudaFuncSetAttribute(megaB_kernel,
        cudaFuncAttributeMaxDynamicSharedMemorySize, MB_TOT);
    cudaFuncSetAttribute(inter_hmma_kernel,
        cudaFuncAttributeMaxDynamicSharedMemorySize, SM_TOT);

    prep_weights<<<(W_TOTAL+255)/256, 256>>>(ws1, ws2, wu2, wi3, wu1, wi1, wi2);

    const float* h = slots;
    for (int it = 0; it < 2; it++) {
        megaA_kernel<<<128, 256, MA_TOT>>>(h, ls_g, ls_b, bs1, bs2, bi1,
                                           HDS, Ab, Bb);
        inter_hmma_kernel<<<dim3(BB, TT, 2), 256, SM_TOT>>>(
            Ab, Bb, bi2, ep, et, Sb, W);
        float* hnew = (it == 0) ? H : out;
        megaB_kernel<<<128, 256, MB_TOT>>>(Sb, W, bi3, HDS, lu_g, lu_b,
                                           bu1, bu2, h, hnew);
        h = H;
    }
}

// round 10
// speedup vs baseline: 1.2768x; 1.0837x over previous
#include <cuda_runtime.h>
#include <cuda_bf16.h>
#include <cstdint>

// Problem constants
#define BB 64
#define KK 64
#define DD 128
#define HH 128
#define TT 4
#define ROWS (BB*KK)        // 4096
#define EPSLN 1e-5f

// ---------------- scratch (no allocations allowed) ----------------
__device__ __align__(16) float g_HDS[ROWS*DD];
__device__ __align__(16) float g_H  [ROWS*DD];
__device__ __align__(16) float g_W  [ROWS*TT];          // [row][tau]
__device__ __align__(16) __nv_bfloat16 g_Ab [TT*ROWS*HH];
__device__ __align__(16) __nv_bfloat16 g_Bb [TT*ROWS*HH];
__device__ __align__(16) __nv_bfloat16 g_Sb [ROWS*TT*HH];   // [row][tau*128+n]

// prepped weights: bf16, [n][k-pair] chunked (4096 words per 64-k chunk)
#define W_WS1   0
#define W_WS2   8192
#define W_WU2   16384
#define W_WI3   24576
#define W_WU1   57344
#define W_WI1   73728
#define W_WI2F  139264
#define W_TOTAL 172032
__device__ __align__(16) uint32_t g_Wp[W_TOTAL];

// ---------------- helpers ----------------
__device__ __forceinline__ uint32_t pk2(float lo, float hi){
    __nv_bfloat162 v = __floats2bfloat162_rn(lo, hi);
    return *(uint32_t*)&v;
}
__device__ __forceinline__ uint32_t addrelu2(uint32_t a, uint32_t b){
    __nv_bfloat162 av = *(__nv_bfloat162*)&a;
    __nv_bfloat162 bv = *(__nv_bfloat162*)&b;
    __nv_bfloat162 z  = __float2bfloat162_rn(0.f);
    __nv_bfloat162 r  = __hmax2(__hadd2(av, bv), z);
    return *(uint32_t*)&r;
}
__device__ __forceinline__ void mma16816(float c[4], const uint32_t a[4],
                                         uint32_t b0, uint32_t b1){
    asm volatile(
        "mma.sync.aligned.m16n8k16.row.col.f32.bf16.bf16.f32 "
        "{%0,%1,%2,%3}, {%4,%5,%6,%7}, {%8,%9}, {%0,%1,%2,%3};\n"
        : "+f"(c[0]), "+f"(c[1]), "+f"(c[2]), "+f"(c[3])
        : "r"(a[0]), "r"(a[1]), "r"(a[2]), "r"(a[3]), "r"(b0), "r"(b1));
}
__device__ __forceinline__ void ldmx4(uint32_t r[4], uint32_t a){
    asm volatile("ldmatrix.sync.aligned.m8n8.x4.shared.b16 {%0,%1,%2,%3}, [%4];"
        : "=r"(r[0]), "=r"(r[1]), "=r"(r[2]), "=r"(r[3]) : "r"(a));
}
__device__ __forceinline__ uint32_t s2u(const void* p){
    return (uint32_t)__cvta_generic_to_shared((void*)p);
}
__device__ __forceinline__ void cpa16(uint32_t dst, const void* src){
    asm volatile("cp.async.cg.shared.global [%0], [%1], 16;"
                 :: "r"(dst), "l"(src) : "memory");
}
#define CPA_COMMIT() asm volatile("cp.async.commit_group;" ::: "memory")
#define CPA_WAIT1()  asm volatile("cp.async.wait_group 1;" ::: "memory")

// ---------------- weight prep: fp32 [K][128] -> bf16 [chunk][n][kw] ---------
__global__ void __launch_bounds__(256) prep_weights(
    const float* __restrict__ ws1, const float* __restrict__ ws2,
    const float* __restrict__ wu2, const float* __restrict__ wi3,
    const float* __restrict__ wu1, const float* __restrict__ wi1,
    const float* __restrict__ wi2)
{
    int idx = blockIdx.x*256 + threadIdx.x;
    if (idx >= W_TOTAL) return;
    const float* src;
    int local;
    if (idx < W_WS2)       { src = ws1; local = idx - W_WS1; }
    else if (idx < W_WU2)  { src = ws2; local = idx - W_WS2; }
    else if (idx < W_WI3)  { src = wu2; local = idx - W_WU2; }
    else if (idx < W_WU1)  { src = wi3; local = idx - W_WI3; }
    else if (idx < W_WI1)  { src = wu1; local = idx - W_WU1; }
    else if (idx < W_WI2F) {
        int l = idx - W_WI1;
        int tau = l >> 14;
        src = wi1 + (size_t)tau*256*128;
        local = l & 16383;
    } else {
        int l = idx - W_WI2F;
        int tau = l >> 13;
        int r = l & 8191;
        int n = r >> 6, w = r & 63;
        const float* s = wi2 + (size_t)tau*16384;
        g_Wp[idx] = pk2(s[(size_t)(2*w)*128 + n], s[(size_t)(2*w+1)*128 + n]);
        return;
    }
    int c = local >> 12;
    int r = local & 4095;
    int n = r >> 5, w = r & 31;
    int k = c*64 + 2*w;
    g_Wp[idx] = pk2(src[(size_t)k*128 + n], src[(size_t)(k+1)*128 + n]);
}

// ---------------- pipelined GEMM primitives (32 rows x 128 n x 64 k) --------
#define GSTR 36

__device__ __forceinline__ void prefW(uint32_t dstBase,
                                      const uint32_t* __restrict__ Wg, int tid){
    #pragma unroll
    for (int l = 0; l < 4; l++) {
        int u = tid + l*256;
        int n = u >> 3, w0 = (u & 7)*4;
        cpa16(dstBase + (uint32_t)(n*GSTR + w0)*4, Wg + u*4);
    }
}
// full 32-row x 64-k bf16 tile: 256 uint4, one per thread
__device__ __forceinline__ void prefS(uint32_t dstBase,
                                      const __nv_bfloat16* __restrict__ Sb,
                                      int rowBase, int c8, int tid){
    int lr = tid >> 3, uu = tid & 7;   // lr in [0,31], uu in [0,7]
    cpa16(dstBase + (uint32_t)(lr*36 + uu*4)*4,
          (const uint4*)Sb + (size_t)(rowBase+lr)*64 + c8*8 + uu);
}
__device__ __forceinline__ void cmpW(
    float (&c)[4][4], uint32_t smB, int wtOff,
    int aOff, int astr, int aChunkOff, int tid)
{
    int lane = tid & 31, wid = tid >> 5;
    int warp_m = wid >> 2, warp_n = wid & 3;
    int lA_row = lane & 15, lA_kw = (lane >> 4) << 2;
    int lB_row = (lane & 7) + ((lane >> 4) << 3);
    int lB_kw  = ((lane >> 3) & 1) << 2;
    uint32_t AsB = smB + aOff, WtB = smB + (uint32_t)wtOff;
    #pragma unroll
    for (int kk = 0; kk < 4; kk++) {
        uint32_t wf0[4], wf1[4], a[4];
        ldmx4(wf0, WtB + ((warp_n*32 + lB_row)*GSTR + kk*8 + lB_kw)*4);
        ldmx4(wf1, WtB + ((warp_n*32 + 16 + lB_row)*GSTR + kk*8 + lB_kw)*4);
        ldmx4(a, AsB + ((warp_m*16 + lA_row)*astr + aChunkOff + kk*8 + lA_kw)*4);
        mma16816(c[0], a, wf0[0], wf0[1]);
        mma16816(c[1], a, wf0[2], wf0[3]);
        mma16816(c[2], a, wf1[0], wf1[1]);
        mma16816(c[3], a, wf1[2], wf1[3]);
    }
}

// ---------------- megaA: LN128 + self-MLP + wi1 (pipelined) -----------------
#define MA_HS   0                       // 16384
#define MA_XN   16384                   // 8704
#define MA_HB   25088                   // 8704
#define MA_T1   33792                   // 8704
#define MA_W0   42496                   // 18432
#define MA_W1   60928                   // 18432
#define MA_TOT  79360

__global__ void __launch_bounds__(256) megaA_kernel(
    const float* __restrict__ h,
    const float* __restrict__ ls_g, const float* __restrict__ ls_b,
    const float* __restrict__ bs1, const float* __restrict__ bs2,
    const float* __restrict__ bi1,
    float* __restrict__ HDS, __nv_bfloat16* __restrict__ Ab,
    __nv_bfloat16* __restrict__ Bb)
{
    extern __shared__ char sm[];
    float* Hs = (float*)(sm + MA_HS);
    uint32_t* XN = (uint32_t*)(sm + MA_XN);
    uint32_t* HB = (uint32_t*)(sm + MA_HB);
    uint32_t* T1 = (uint32_t*)(sm + MA_T1);
    uint32_t smB = s2u(sm);
    int tid = threadIdx.x, lane = tid & 31, wid = tid >> 5;
    int rowBase = blockIdx.x * 32;
    int g = lane >> 2, q4 = lane & 3;
    int warp_m = wid >> 2, warp_n = wid & 3;
    int row0 = warp_m*16 + g, row1 = row0 + 8;

    prefW(smB + MA_W0, g_Wp + W_WS1, tid);        CPA_COMMIT();
    prefW(smB + MA_W1, g_Wp + W_WS1 + 4096, tid); CPA_COMMIT();

    #pragma unroll
    for (int l = 0; l < 4; l++) {
        int u = tid + l*256;
        int r = u >> 5, q = u & 31;
        *(float4*)&Hs[r*128 + q*4] =
            *(const float4*)&h[(size_t)(rowBase+r)*128 + q*4];
    }
    __syncthreads();
    {
        float4 gg = ((const float4*)ls_g)[lane];
        float4 bb = ((const float4*)ls_b)[lane];
        #pragma unroll
        for (int p = 0; p < 4; p++) {
            int r = wid + p*8;
            float4 v = *(float4*)&Hs[r*128 + lane*4];
            float s = v.x + v.y + v.z + v.w;
            #pragma unroll
            for (int o = 16; o; o >>= 1) s += __shfl_xor_sync(0xffffffffu, s, o);
            float mu = s * (1.0f/128.0f);
            float dx = v.x-mu, dy = v.y-mu, dz = v.z-mu, dw = v.w-mu;
            float q = dx*dx + dy*dy + dz*dz + dw*dw;
            #pragma unroll
            for (int o = 16; o; o >>= 1) q += __shfl_xor_sync(0xffffffffu, q, o);
            float rs = rsqrtf(q * (1.0f/128.0f) + EPSLN);
            XN[r*68 + lane*2]   = pk2(dx*rs*gg.x + bb.x, dy*rs*gg.y + bb.y);
            XN[r*68 + lane*2+1] = pk2(dz*rs*gg.z + bb.z, dw*rs*gg.w + bb.w);
            HB[r*68 + lane*2]   = pk2(v.x, v.y);
            HB[r*68 + lane*2+1] = pk2(v.z, v.w);
        }
    }

    // ---- unit ws1: T1 = relu(XN@ws1+bs1)   chunks 0,1; prefetch 2,3
    {
        float c[4][4] = {};
        CPA_WAIT1(); __syncthreads();
        cmpW(c, smB, MA_W0, MA_XN, 68, 0, tid);
        __syncthreads();
        prefW(smB + MA_W0, g_Wp + W_WS2, tid); CPA_COMMIT();
        CPA_WAIT1(); __syncthreads();
        cmpW(c, smB, MA_W1, MA_XN, 68, 32, tid);
        #pragma unroll
        for (int nt = 0; nt < 4; nt++) {
            int n0 = warp_n*32 + nt*8 + 2*q4;
            float2 bv = *(const float2*)&bs1[n0];
            T1[row0*68 + (n0>>1)] =
                pk2(fmaxf(c[nt][0]+bv.x,0.f), fmaxf(c[nt][1]+bv.y,0.f));
            T1[row1*68 + (n0>>1)] =
                pk2(fmaxf(c[nt][2]+bv.x,0.f), fmaxf(c[nt][3]+bv.y,0.f));
        }
        __syncthreads();
        prefW(smB + MA_W1, g_Wp + W_WS2 + 4096, tid); CPA_COMMIT();
    }

    // ---- unit ws2: HDS = h + T1@ws2 + bs2   chunks 2,3; prefetch 4,5
    {
        float c[4][4] = {};
        CPA_WAIT1(); __syncthreads();
        cmpW(c, smB, MA_W0, MA_T1, 68, 0, tid);
        __syncthreads();
        prefW(smB + MA_W0, g_Wp + W_WI1, tid); CPA_COMMIT();
        CPA_WAIT1(); __syncthreads();
        cmpW(c, smB, MA_W1, MA_T1, 68, 32, tid);
        #pragma unroll
        for (int nt = 0; nt < 4; nt++) {
            int n0 = warp_n*32 + nt*8 + 2*q4;
            float2 bv = *(const float2*)&bs2[n0];
            float2 h0 = *(float2*)&Hs[row0*128 + n0];
            float2 h1 = *(float2*)&Hs[row1*128 + n0];
            *(float2*)&HDS[(size_t)(rowBase+row0)*128 + n0] =
                make_float2(c[nt][0]+bv.x+h0.x, c[nt][1]+bv.y+h0.y);
            *(float2*)&HDS[(size_t)(rowBase+row1)*128 + n0] =
                make_float2(c[nt][2]+bv.x+h1.x, c[nt][3]+bv.y+h1.y);
        }
        __syncthreads();
        prefW(smB + MA_W1, g_Wp + W_WI1 + 4096, tid); CPA_COMMIT();
    }

    // ---- units wi1 x8: chunks 4..19; prefetch k+2
    #pragma unroll 1
    for (int u = 0; u < 8; u++) {
        float c[4][4] = {};
        CPA_WAIT1(); __syncthreads();
        cmpW(c, smB, MA_W0, MA_HB, 68, 0, tid);
        __syncthreads();
        { int nk = 4 + 2*u + 2;
          if (nk < 20) prefW(smB + MA_W0, g_Wp + W_WI1 + (nk-4)*4096, tid); }
        CPA_COMMIT();
        CPA_WAIT1(); __syncthreads();
        cmpW(c, smB, MA_W1, MA_HB, 68, 32, tid);
        {
            int tau = u >> 1, half = u & 1;
            uint32_t* ob = (uint32_t*)((half ? Bb : Ab) +
                            ((size_t)tau*ROWS + rowBase)*128);
            #pragma unroll
            for (int nt = 0; nt < 4; nt++) {
                int n0 = warp_n*32 + nt*8 + 2*q4;
                float2 bv = half ? make_float2(0.f,0.f)
                                 : *(const float2*)&bi1[tau*128 + n0];
                ob[row0*64 + (n0>>1)] = pk2(c[nt][0]+bv.x, c[nt][1]+bv.y);
                ob[row1*64 + (n0>>1)] = pk2(c[nt][2]+bv.x, c[nt][3]+bv.y);
            }
        }
        __syncthreads();
        { int nk = 4 + 2*u + 3;
          if (nk < 20) prefW(smB + MA_W1, g_Wp + W_WI1 + (nk-4)*4096, tid); }
        CPA_COMMIT();
    }
}

// ---------------- HMMA fused inter kernel (32j x 64n warp tiles) ------------
#define WSTR 68
#define SM_AS   0                       // 17408
#define SM_BS   17408                   // 17408
#define SM_W2   34816                   // 34816
#define SM_WM   69632                   // 16384
#define SM_BI2  86016                   // 512
#define SM_TOT  86528

__global__ void __launch_bounds__(256, 1) inter_hmma_kernel(
    const __nv_bfloat16* __restrict__ gAb, const __nv_bfloat16* __restrict__ gBb,
    const float* __restrict__ bi2,
    const float* __restrict__ ep, const float* __restrict__ et,
    __nv_bfloat16* __restrict__ gSb, float* __restrict__ gW)
{
    extern __shared__ char sm[];
    uint32_t* Asm  = (uint32_t*)(sm + SM_AS);
    uint32_t* Bsm  = (uint32_t*)(sm + SM_BS);
    uint32_t* W2s  = (uint32_t*)(sm + SM_W2);
    float* Wmat = (float*)(sm + SM_WM);    // [i:64][j:64]
    float* bi2s = (float*)(sm + SM_BI2);

    int tid = threadIdx.x, lane = tid & 31, wid = tid >> 5;
    int b = blockIdx.x, tau = blockIdx.y;
    int g = lane >> 2, q4 = lane & 3;
    int warp_p  = wid >> 2;
    int warp_j  = (wid >> 1) & 1;
    int warp_nh = wid & 1;
    int lA_row = lane & 15, lA_kw = (lane >> 4) << 2;
    int lB_row = (lane & 7) + ((lane >> 4) << 3);
    int lB_kw  = ((lane >> 3) & 1) << 2;
    uint32_t BsB = s2u(sm) + SM_BS, W2B = s2u(sm) + SM_W2;

    const uint4* Ag = (const uint4*)(gAb + ((size_t)tau*ROWS + b*64)*128);
    const uint4* Bg = (const uint4*)(gBb + ((size_t)tau*ROWS + b*64)*128);
    #pragma unroll
    for (int l = 0; l < 4; l++) {
        int v = tid + l*256;
        int row = v >> 4, wq = v & 15;
        *(uint4*)&Asm[row*WSTR + wq*4] = Ag[row*16 + wq];
        *(uint4*)&Bsm[row*WSTR + wq*4] = Bg[row*16 + wq];
    }
    {
        const uint4* src = (const uint4*)(g_Wp + W_WI2F + tau*8192);
        #pragma unroll
        for (int l = 0; l < 8; l++) {
            int u = tid + l*256;
            int n = u >> 4, q = u & 15;
            *(uint4*)&W2s[n*WSTR + q*4] = src[u];
        }
    }
    const size_t ebase = (size_t)b*64*64;
    #pragma unroll
    for (int l = 0; l < 16; l++) {
        int q = tid + l*256;
        Wmat[q] = ep[ebase + q] * et[(ebase + q)*4 + tau];
    }
    if (tid < 128) bi2s[tid] = bi2[tau*128 + tid];
    __syncthreads();

    if (tid < 64) {
        float s = 0.f;
        #pragma unroll 8
        for (int i = 0; i < 64; i++) s += Wmat[i*64 + tid];
        gW[(size_t)(b*64 + tid)*4 + tau] = s;
    }

    float bi2v[8][2];
    #pragma unroll
    for (int nn = 0; nn < 8; nn++) {
        int n0 = warp_nh*64 + nn*8 + 2*q4;
        bi2v[nn][0] = bi2s[n0];
        bi2v[nn][1] = bi2s[n0 + 1];
    }

    float S[2][8][4] = {};

    for (int it = 0; it < 32; it++) {
        int i = 2*it + warp_p;
        float c[2][8][4] = {};
        #pragma unroll
        for (int kk = 0; kk < 8; kk++) {
            uint32_t aw0 = Asm[i*WSTR + kk*8 + q4];
            uint32_t aw1 = Asm[i*WSTR + kk*8 + 4 + q4];
            uint32_t wf[4][4];
            #pragma unroll
            for (int nf = 0; nf < 4; nf++)
                ldmx4(wf[nf], W2B + ((warp_nh*64 + nf*16 + lB_row)*WSTR
                                     + kk*8 + lB_kw)*4);
            #pragma unroll
            for (int mt = 0; mt < 2; mt++) {
                uint32_t xb[4], x[4];
                ldmx4(xb, BsB + ((warp_j*32 + mt*16 + lA_row)*WSTR
                                 + kk*8 + lA_kw)*4);
                x[0] = addrelu2(xb[0], aw0);
                x[1] = addrelu2(xb[1], aw0);
                x[2] = addrelu2(xb[2], aw1);
                x[3] = addrelu2(xb[3], aw1);
                #pragma unroll
                for (int nf = 0; nf < 4; nf++) {
                    mma16816(c[mt][2*nf],   x, wf[nf][0], wf[nf][1]);
                    mma16816(c[mt][2*nf+1], x, wf[nf][2], wf[nf][3]);
                }
            }
        }
        #pragma unroll
        for (int mt = 0; mt < 2; mt++) {
            int jr = warp_j*32 + mt*16 + g;
            float w0 = Wmat[i*64 + jr];
            float w1 = Wmat[i*64 + jr + 8];
            #pragma unroll
            for (int nn = 0; nn < 8; nn++) {
                S[mt][nn][0] += w0*fmaxf(c[mt][nn][0] + bi2v[nn][0], 0.f);
                S[mt][nn][1] += w0*fmaxf(c[mt][nn][1] + bi2v[nn][1], 0.f);
                S[mt][nn][2] += w1*fmaxf(c[mt][nn][2] + bi2v[nn][0], 0.f);
                S[mt][nn][3] += w1*fmaxf(c[mt][nn][3] + bi2v[nn][1], 0.f);
            }
        }
    }

    // combine sender parities via smem (reuse W2 area: 64 rows x 132 floats)
    float* Sout = (float*)(sm + SM_W2);
    __syncthreads();
    if (warp_p == 0) {
        #pragma unroll
        for (int mt = 0; mt < 2; mt++) {
            int j = warp_j*32 + mt*16 + g;
            #pragma unroll
            for (int nn = 0; nn < 8; nn++) {
                int n = warp_nh*64 + nn*8 + 2*q4;
                *(float2*)&Sout[j*132 + n] =
                    make_float2(S[mt][nn][0], S[mt][nn][1]);
                *(float2*)&Sout[(j+8)*132 + n] =
                    make_float2(S[mt][nn][2], S[mt][nn][3]);
            }
        }
    }
    __syncthreads();
    if (warp_p == 1) {
        #pragma unroll
        for (int mt = 0; mt < 2; mt++) {
            int j = warp_j*32 + mt*16 + g;
            #pragma unroll
            for (int nn = 0; nn < 8; nn++) {
                int n = warp_nh*64 + nn*8 + 2*q4;
                float2 v0 = *(float2*)&Sout[j*132 + n];
                v0.x += S[mt][nn][0]; v0.y += S[mt][nn][1];
                *(float2*)&Sout[j*132 + n] = v0;
                float2 v1 = *(float2*)&Sout[(j+8)*132 + n];
                v1.x += S[mt][nn][2]; v1.y += S[mt][nn][3];
                *(float2*)&Sout[(j+8)*132 + n] = v1;
            }
        }
    }
    __syncthreads();
    for (int q = tid; q < 2048; q += 256) {
        int j = q >> 5, w = q & 31;
        float4 v = *(float4*)&Sout[j*132 + w*4];
        uint2 u = make_uint2(pk2(v.x, v.y), pk2(v.z, v.w));
        *(uint2*)&gSb[(size_t)(b*64 + j)*512 + tau*128 + w*4] = u;
    }
}

// ---------------- megaB: wi3 GEMM + LN256 + update MLP (pipelined) ----------
// chunk schedule: 0-7 WI3 (+S tiles), 8-11 WU1, 12-13 WU2; buffer = chunk&1;
// each compute iteration prefetches chunk k+2 and commits exactly one group.
#define MB_AS0  0                       // 4608
#define MB_AS1  4608                    // 4608
#define MB_DI   9216                    // 16896
#define MB_CN   26112                   // 16896
#define MB_T1   43008                   // 8704
#define MB_W0   51712                   // 18432
#define MB_W1   70144                   // 18432
#define MB_TOT  88576

__global__ void __launch_bounds__(256) megaB_kernel(
    const __nv_bfloat16* __restrict__ Sb, const float* __restrict__ Wq,
    const float* __restrict__ bi3, const float* __restrict__ HDS,
    const float* __restrict__ lu_g, const float* __restrict__ lu_b,
    const float* __restrict__ bu1, const float* __restrict__ bu2,
    const float* __restrict__ hResid, float* __restrict__ hOut)
{
    extern __shared__ char sm[];
    float*    DIs = (float*)(sm + MB_DI);
    uint32_t* CN = (uint32_t*)(sm + MB_CN);
    uint32_t* T1 = (uint32_t*)(sm + MB_T1);
    uint32_t smB = s2u(sm);
    int tid = threadIdx.x, lane = tid & 31, wid = tid >> 5;
    int rowBase = blockIdx.x * 32;
    int g = lane >> 2, q4 = lane & 3;
    int warp_m = wid >> 2, warp_n = wid & 3;
    int row0 = warp_m*16 + g, row1 = row0 + 8;

    prefW(smB + MB_W0, g_Wp + W_WI3, tid);
    prefS(smB + MB_AS0, Sb, rowBase, 0, tid);
    CPA_COMMIT();
    prefW(smB + MB_W1, g_Wp + W_WI3 + 4096, tid);
    prefS(smB + MB_AS1, Sb, rowBase, 1, tid);
    CPA_COMMIT();

    // ---- unit wi3: DI = Sb @ wi3 (K=512) + wsum*bi3 -> smem fp32
    {
        float c[4][4] = {};
        #pragma unroll 1
        for (int c8 = 0; c8 < 8; c8++) {
            int buf = c8 & 1;
            CPA_WAIT1(); __syncthreads();
            cmpW(c, smB, buf ? MB_W1 : MB_W0, buf ? MB_AS1 : MB_AS0, 36, 0, tid);
            if (c8 == 7) {
                float4 wa = *(const float4*)&Wq[(size_t)(rowBase+row0)*4];
                float4 wb = *(const float4*)&Wq[(size_t)(rowBase+row1)*4];
                #pragma unroll
                for (int nt = 0; nt < 4; nt++) {
                    int n0 = warp_n*32 + nt*8 + 2*q4;
                    float2 v0 = make_float2(c[nt][0], c[nt][1]);
                    float2 v1 = make_float2(c[nt][2], c[nt][3]);
                    #pragma unroll
                    for (int t = 0; t < 4; t++) {
                        float wta = (t==0)?wa.x:(t==1)?wa.y:(t==2)?wa.z:wa.w;
                        float wtb = (t==0)?wb.x:(t==1)?wb.y:(t==2)?wb.z:wb.w;
                        float2 rb = *(const float2*)&bi3[t*128 + n0];
                        v0.x += wta*rb.x; v0.y += wta*rb.y;
                        v1.x += wtb*rb.x; v1.y += wtb*rb.y;
                    }
                    *(float2*)&DIs[row0*132 + n0] = v0;
                    *(float2*)&DIs[row1*132 + n0] = v1;
                }
            }
            __syncthreads();
            int nk = c8 + 2;
            if (nk < 8) {
                prefW(smB + (buf ? MB_W1 : MB_W0), g_Wp + W_WI3 + nk*4096, tid);
                prefS(smB + (buf ? MB_AS1 : MB_AS0), Sb, rowBase, nk, tid);
            } else {
                // chunks 8,9 = WU1 chunks 0,1
                prefW(smB + (buf ? MB_W1 : MB_W0), g_Wp + W_WU1 + (nk-8)*4096, tid);
            }
            CPA_COMMIT();
        }
    }

    // ---- LN256 over [HDS (gmem), DIs (smem)] -> CN bf16 (stride 132 words)
    {
        float4 g0 = ((const float4*)lu_g)[lane];
        float4 g1 = ((const float4*)lu_g)[32 + lane];
        float4 c0 = ((const float4*)lu_b)[lane];
        float4 c1 = ((const float4*)lu_b)[32 + lane];
        #pragma unroll
        for (int p = 0; p < 4; p++) {
            int r = wid + p*8;
            float4 v0 = *(const float4*)&HDS[(size_t)(rowBase+r)*128 + lane*4];
            float4 v1 = *(float4*)&DIs[r*132 + lane*4];
            float s = v0.x+v0.y+v0.z+v0.w + v1.x+v1.y+v1.z+v1.w;
            #pragma unroll
            for (int o = 16; o; o >>= 1) s += __shfl_xor_sync(0xffffffffu, s, o);
            float mu = s * (1.0f/256.0f);
            float a0=v0.x-mu, a1=v0.y-mu, a2=v0.z-mu, a3=v0.w-mu;
            float b0=v1.x-mu, b1=v1.y-mu, b2=v1.z-mu, b3=v1.w-mu;
            float q = a0*a0+a1*a1+a2*a2+a3*a3 + b0*b0+b1*b1+b2*b2+b3*b3;
            #pragma unroll
            for (int o = 16; o; o >>= 1) q += __shfl_xor_sync(0xffffffffu, q, o);
            float rs = rsqrtf(q * (1.0f/256.0f) + EPSLN);
            CN[r*132 + lane*2]        = pk2(a0*rs*g0.x + c0.x, a1*rs*g0.y + c0.y);
            CN[r*132 + lane*2 + 1]    = pk2(a2*rs*g0.z + c0.z, a3*rs*g0.w + c0.w);
            CN[r*132 + 64 + lane*2]   = pk2(b0*rs*g1.x + c1.x, b1*rs*g1.y + c1.y);
            CN[r*132 + 64 + lane*2+1] = pk2(b2*rs*g1.z + c1.z, b3*rs*g1.w + c1.w);
        }
    }
    // CN smem visibility covered by WAIT1+__syncthreads at next chunk

    // ---- unit wu1: T1 = relu(CN @ wu1 + bu1)  chunks 8..11; prefetch 10..13
    {
        float c[4][4] = {};
        #pragma unroll 1
        for (int ch = 0; ch < 4; ch++) {
            int buf = ch & 1;
            CPA_WAIT1(); __syncthreads();
            cmpW(c, smB, buf ? MB_W1 : MB_W0, MB_CN, 132, ch*32, tid);
            if (ch == 3) {
                #pragma unroll
                for (int nt = 0; nt < 4; nt++) {
                    int n0 = warp_n*32 + nt*8 + 2*q4;
                    float2 bv = *(const float2*)&bu1[n0];
                    T1[row0*68 + (n0>>1)] =
                        pk2(fmaxf(c[nt][0]+bv.x,0.f), fmaxf(c[nt][1]+bv.y,0.f));
                    T1[row1*68 + (n0>>1)] =
                        pk2(fmaxf(c[nt][2]+bv.x,0.f), fmaxf(c[nt][3]+bv.y,0.f));
                }
            }
            __syncthreads();
            int nk = 10 + ch;   // global chunk id of the prefetch target
            if (nk < 12)
                prefW(smB + (buf ? MB_W1 : MB_W0),
                      g_Wp + W_WU1 + (nk-8)*4096, tid);
            else
                prefW(smB + (buf ? MB_W1 : MB_W0),
                      g_Wp + W_WU2 + (nk-12)*4096, tid);
            CPA_COMMIT();
        }
    }

    // ---- unit wu2: hOut = hResid + T1 @ wu2 + bu2 (chunks 12,13)
    {
        float c[4][4] = {};
        CPA_WAIT1(); __syncthreads();
        cmpW(c, smB, MB_W0, MB_T1, 68, 0, tid);
        __syncthreads();
        CPA_COMMIT();
        CPA_WAIT1(); __syncthreads();
        cmpW(c, smB, MB_W1, MB_T1, 68, 32, tid);
        #pragma unroll
        for (int nt = 0; nt < 4; nt++) {
            int n0 = warp_n*32 + nt*8 + 2*q4;
            float2 bv = *(const float2*)&bu2[n0];
            float2 h0 = *(const float2*)&hResid[(size_t)(rowBase+row0)*128 + n0];
            float2 h1 = *(const float2*)&hResid[(size_t)(rowBase+row1)*128 + n0];
            *(float2*)&hOut[(size_t)(rowBase+row0)*128 + n0] =
                make_float2(c[nt][0]+bv.x+h0.x, c[nt][1]+bv.y+h0.y);
            *(float2*)&hOut[(size_t)(rowBase+row1)*128 + n0] =
                make_float2(c[nt][2]+bv.x+h1.x, c[nt][3]+bv.y+h1.y);
        }
    }
}

// ---------------- host orchestration ----------------
extern "C" void kernel_launch(void* const* d_in, const int* in_sizes, int n_in,
                              void* d_out, int out_size)
{
    const float* slots = (const float*)d_in[0];
    const float* ep    = (const float*)d_in[1];
    const float* et    = (const float*)d_in[2];
    const float* ls_g  = (const float*)d_in[3];
    const float* ls_b  = (const float*)d_in[4];
    const float* ws1   = (const float*)d_in[5];
    const float* bs1   = (const float*)d_in[6];
    const float* ws2   = (const float*)d_in[7];
    const float* bs2   = (const float*)d_in[8];
    const float* wi1   = (const float*)d_in[9];
    const float* bi1   = (const float*)d_in[10];
    const float* wi2   = (const float*)d_in[11];
    const float* bi2   = (const float*)d_in[12];
    const float* wi3   = (const float*)d_in[13];
    const float* bi3   = (const float*)d_in[14];
    const float* lu_g  = (const float*)d_in[15];
    const float* lu_b  = (const float*)d_in[16];
    const float* wu1   = (const float*)d_in[17];
    const float* bu1   = (const float*)d_in[18];
    const float* wu2   = (const float*)d_in[19];
    const float* bu2   = (const float*)d_in[20];
    float* out = (float*)d_out;

    float *HDS, *H, *W;
    __nv_bfloat16 *Ab, *Bb, *Sb;
    cudaGetSymbolAddress((void**)&HDS, g_HDS);
    cudaGetSymbolAddress((void**)&H,   g_H);
    cudaGetSymbolAddress((void**)&W,   g_W);
    cudaGetSymbolAddress((void**)&Ab,  g_Ab);
    cudaGetSymbolAddress((void**)&Bb,  g_Bb);
    cudaGetSymbolAddress((void**)&Sb,  g_Sb);

    cudaFuncSetAttribute(megaA_kernel,
        cudaFuncAttributeMaxDynamicSharedMemorySize, MA_TOT);
    cudaFuncSetAttribute(megaB_kernel,
        cudaFuncAttributeMaxDynamicSharedMemorySize, MB_TOT);
    cudaFuncSetAttribute(inter_hmma_kernel,
        cudaFuncAttributeMaxDynamicSharedMemorySize, SM_TOT);

    prep_weights<<<(W_TOTAL+255)/256, 256>>>(ws1, ws2, wu2, wi3, wu1, wi1, wi2);

    const float* h = slots;
    for (int it = 0; it < 2; it++) {
        megaA_kernel<<<128, 256, MA_TOT>>>(h, ls_g, ls_b, bs1, bs2, bi1,
                                           HDS, Ab, Bb);
        inter_hmma_kernel<<<dim3(BB, TT), 256, SM_TOT>>>(
            Ab, Bb, bi2, ep, et, Sb, W);
        float* hnew = (it == 0) ? H : out;
        megaB_kernel<<<128, 256, MB_TOT>>>(Sb, W, bi3, HDS, lu_g, lu_b,
                                           bu1, bu2, h, hnew);
        h = H;
    }
}